// round 15
// baseline (speedup 1.0000x reference)
#include <cuda_runtime.h>
#include <math.h>

#define Bq 512
#define Sq 4096
#define Dq 128
#define Vq 6
#define Kq 409

// Precomputed per-token-value tables
__device__ float g_score[Vq];
__device__ float g_attC1[Vq * 64];   // att_v @ C1  (classifier layer-1 fold)

// ---------------------------------------------------------------------------
// Kernel 1: precompute — 6 blocks (one per token value) x 256 threads. (R13)
// ---------------------------------------------------------------------------
__global__ __launch_bounds__(256) void precompute_kernel(
    const float* __restrict__ emb,
    const float* __restrict__ W1, const float* __restrict__ b1,
    const float* __restrict__ W2, const float* __restrict__ b2,
    const float* __restrict__ W3, const float* __restrict__ b3,
    const float* __restrict__ A1, const float* __restrict__ a1,
    const float* __restrict__ A2, const float* __restrict__ a2,
    const float* __restrict__ C1)
{
#if __CUDA_ARCH__ >= 900
    cudaTriggerProgrammaticLaunchCompletion();
#endif
    const int v = blockIdx.x;
    const int t = threadIdx.x;  // 256 threads
    __shared__ float e[Dq];
    __shared__ float h1[64];
    __shared__ float g1[64];
    __shared__ float h2[32];
    __shared__ float att_s[Dq];

    if (t < Dq) e[t] = emb[v * Dq + t];
    __syncthreads();

    // layer 1: both W1 and A1. 256 threads = 2 mats x 64 neurons x 2 halves.
    {
        const int mat = t >> 7;
        const int n   = (t & 127) >> 1;
        const int p   = t & 1;
        const float* M = mat ? A1 : W1;
        float s = 0.f;
        const int base = p * 64;
        #pragma unroll
        for (int i = 0; i < 64; i++)
            s += e[base + i] * M[(base + i) * 64 + n];
        s += __shfl_xor_sync(0xffffffff, s, 1);
        if (p == 0) {
            if (mat == 0) h1[n] = fmaxf(s + b1[n], 0.f);
            else          g1[n] = fmaxf(s + a1[n], 0.f);
        }
    }
    __syncthreads();

    // layer 2 (W2): 32 neurons x 4 threads (threads 0..127)
    if (t < 128) {
        const int n = t >> 2, p = t & 3;
        float s = 0.f;
        const int base = p * 16;
        #pragma unroll
        for (int i = 0; i < 16; i++)
            s += h1[base + i] * W2[(base + i) * 32 + n];
        s += __shfl_xor_sync(0xffffffff, s, 1);
        s += __shfl_xor_sync(0xffffffff, s, 2);
        if (p == 0) h2[n] = fmaxf(s + b2[n], 0.f);
    }
    // A2: 128 outputs x 2 threads
    {
        const int j = t >> 1, p = t & 1;
        float s = 0.f;
        const int base = p * 32;
        #pragma unroll
        for (int i = 0; i < 32; i++)
            s += g1[base + i] * A2[(base + i) * Dq + j];
        s += __shfl_xor_sync(0xffffffff, s, 1);
        if (p == 0) att_s[j] = s + a2[j];
    }
    __syncthreads();

    // layer 3: warp 0 -> sigmoid score
    if (t < 32) {
        float z = h2[t] * W3[t];
        #pragma unroll
        for (int d = 16; d >= 1; d >>= 1) z += __shfl_xor_sync(0xffffffff, z, d);
        if (t == 0) g_score[v] = 1.f / (1.f + expf(-(z + b3[0])));
    }

    // attC1[v][n] = att_v @ C1[:,n]: 64 neurons x 4 threads
    {
        const int n = t >> 2, p = t & 3;
        float s = 0.f;
        const int base = p * 32;
        #pragma unroll
        for (int i = 0; i < 32; i++)
            s += att_s[base + i] * C1[(base + i) * 64 + n];
        s += __shfl_xor_sync(0xffffffff, s, 1);
        s += __shfl_xor_sync(0xffffffff, s, 2);
        if (p == 0) g_attC1[v * 64 + n] = s;
    }
}

// ---------------------------------------------------------------------------
// Kernel 2: cluster of 2 CTAs per batch row; each CTA handles 2048 tokens
// (256 threads x 8). Packed-u64 count exchange over DSMEM; top_idx written
// directly to global (scattered 4B stores).
// ---------------------------------------------------------------------------
__global__ __launch_bounds__(256, 5) void main_kernel(
    const int* __restrict__ x,
    const float* __restrict__ c1,
    const float* __restrict__ C2, const float* __restrict__ c2,
    float* __restrict__ out)
{
    const int b = blockIdx.x >> 1;
    const int t = threadIdx.x;  // 256 threads
    const int w = t >> 5, l = t & 31;
    unsigned rank;
    asm("mov.u32 %0, %%cluster_ctarank;" : "=r"(rank));

    __shared__ unsigned long long wtot[8];
    __shared__ unsigned long long s_ctot;

    const int half = rank ? (Sq / 2) : 0;

    // ---------- score-independent front half (overlaps precompute) ----------
    const int4* xb = (const int4*)(x + (size_t)b * Sq + half);

    int4 P[2];
    unsigned long long hist = 0ull;
    #pragma unroll
    for (int i = 0; i < 2; i++) {
        int4 p = xb[t * 2 + i];
        P[i] = p;
        hist += 1ull << (p.x * 10);
        hist += 1ull << (p.y * 10);
        hist += 1ull << (p.z * 10);
        hist += 1ull << (p.w * 10);
    }

    // warp-level packed inclusive scan (10-bit fields)
    unsigned long long run = hist;
    #pragma unroll
    for (int d = 1; d < 32; d <<= 1) {
        unsigned long long o = __shfl_up_sync(0xffffffff, run, d);
        if (l >= d) run += o;
    }
    const unsigned long long excl = run - hist;
    if (l == 31) wtot[w] = run;
    __syncthreads();  // barrier 1

    // cross-warp within CTA
    unsigned long long pre = 0ull, all = 0ull;
    #pragma unroll
    for (int ww = 0; ww < 8; ww++) {
        unsigned long long tw = wtot[ww];
        if (ww < w) pre += tw;
        all += tw;
    }
    if (t == 0) s_ctot = all;

    // ---------- cluster exchange of packed per-value totals ----------
    asm volatile("barrier.cluster.arrive.aligned;" ::: "memory");
    asm volatile("barrier.cluster.wait.aligned;" ::: "memory");
    unsigned long long peer_all;
    {
        unsigned my = (unsigned)__cvta_generic_to_shared(&s_ctot);
        unsigned pa;
        asm volatile("mapa.shared::cluster.u32 %0, %1, %2;"
                     : "=r"(pa) : "r"(my), "r"(rank ^ 1u));
        asm volatile("ld.shared::cluster.u64 %0, [%1];"
                     : "=l"(peer_all) : "r"(pa));
    }
    // peer smem no longer needed; arrive now, wait at kernel end
    asm volatile("barrier.cluster.arrive.aligned;" ::: "memory");

    // row-global packed rank base + row totals
    unsigned long long pcnt = pre + excl + (rank ? peer_all : 0ull);
    const unsigned long long row_all = all + peer_all;
    int tot[Vq];
    #pragma unroll
    for (int v = 0; v < Vq; v++)
        tot[v] = (int)((row_all >> (v * 10)) & 0x3FF);

    // ---------- wait for precompute results ----------
#if __CUDA_ARCH__ >= 900
    cudaGridDependencySynchronize();
#endif

    float sc[Vq];
    #pragma unroll
    for (int v = 0; v < Vq; v++) sc[v] = g_score[v];

    // lane-resident score for dynamic gather via shfl
    const int v_me = (l < Vq) ? l : (Vq - 1);
    const float scf = sc[v_me];

    // per-lane rank offset over row totals
    int offraw_lane = 0;
    #pragma unroll
    for (int u = 0; u < Vq; u++) {
        bool prec = (u != v_me) &&
                    ((sc[u] > sc[v_me]) || (sc[u] == sc[v_me] && u < v_me));
        offraw_lane += prec ? tot[u] : 0;
    }

    // ---------- fused fs-store + compaction (direct global scatter) ----------
    float* fs   = out + Bq + (size_t)Bq * Kq + (size_t)b * Sq + half;
    float* oidx = out + Bq + (size_t)b * Kq;
    #pragma unroll
    for (int i = 0; i < 2; i++) {
        const int* pv = (const int*)&P[i];
        float4 f;
        float* fp = (float*)&f;
        #pragma unroll
        for (int j = 0; j < 4; j++) {
            const int vv = pv[j];
            fp[j] = __shfl_sync(0xffffffff, scf, vv);
            const int ofr = __shfl_sync(0xffffffff, offraw_lane, vv);
            const int sh = vv * 10;
            const int rk = (int)((pcnt >> sh) & 0x3FF);
            pcnt += 1ull << sh;
            const int pos = ofr + rk;
            if (pos < Kq)
                oidx[pos] = (float)(half + t * 8 + i * 4 + j);
        }
        ((float4*)fs)[t * 2 + i] = f;
    }

    // ---------- folded classifier epilogue (rank 0, warp 0 only) ----------
    if (rank == 0 && w == 0) {
        float takef[Vq];
        #pragma unroll
        for (int v = 0; v < Vq; v++) {
            const int ofr = __shfl_sync(0xffffffff, offraw_lane, v);
            takef[v] = (float)max(0, min(Kq - ofr, tot[v]));
        }
        const float invK = 1.f / (float)Kq;
        float zacc = 0.f;
        #pragma unroll
        for (int hh = 0; hh < 2; hh++) {
            const int n = l + hh * 32;
            float s = 0.f;
            #pragma unroll
            for (int v = 0; v < Vq; v++)
                s += takef[v] * g_attC1[v * 64 + n];
            const float h = fmaxf(fmaf(s, invK, c1[n]), 0.f);
            zacc += h * C2[n];
        }
        #pragma unroll
        for (int d = 16; d >= 1; d >>= 1)
            zacc += __shfl_xor_sync(0xffffffff, zacc, d);
        if (l == 0) out[b] = 1.f / (1.f + expf(-(zacc + c2[0])));
    }

    asm volatile("barrier.cluster.wait.aligned;" ::: "memory");
}

extern "C" void kernel_launch(void* const* d_in, const int* in_sizes, int n_in,
                              void* d_out, int out_size) {
    const int*   x   = (const int*)d_in[0];
    const float* emb = (const float*)d_in[1];
    const float* W1  = (const float*)d_in[2];
    const float* b1  = (const float*)d_in[3];
    const float* W2  = (const float*)d_in[4];
    const float* b2  = (const float*)d_in[5];
    const float* W3  = (const float*)d_in[6];
    const float* b3  = (const float*)d_in[7];
    const float* A1  = (const float*)d_in[8];
    const float* a1  = (const float*)d_in[9];
    const float* A2  = (const float*)d_in[10];
    const float* a2  = (const float*)d_in[11];
    const float* C1  = (const float*)d_in[12];
    const float* c1  = (const float*)d_in[13];
    const float* C2  = (const float*)d_in[14];
    const float* c2  = (const float*)d_in[15];
    float* out = (float*)d_out;

    precompute_kernel<<<Vq, 256>>>(emb, W1, b1, W2, b2, W3, b3,
                                   A1, a1, A2, a2, C1);

    // Cluster(2) + PDL launch of main_kernel.
    cudaLaunchConfig_t cfg = {};
    cfg.gridDim  = dim3(Bq * 2, 1, 1);
    cfg.blockDim = dim3(256, 1, 1);
    cfg.dynamicSmemBytes = 0;
    cfg.stream = 0;
    cudaLaunchAttribute attrs[2];
    attrs[0].id = cudaLaunchAttributeClusterDimension;
    attrs[0].val.clusterDim = {2, 1, 1};
    attrs[1].id = cudaLaunchAttributeProgrammaticStreamSerialization;
    attrs[1].val.programmaticStreamSerializationAllowed = 1;
    cfg.attrs = attrs;
    cfg.numAttrs = 2;
    cudaLaunchKernelEx(&cfg, main_kernel, x, c1, C2, c2, out);
}

// round 16
// speedup vs baseline: 1.1555x; 1.1555x over previous
#include <cuda_runtime.h>
#include <math.h>

#define Bq 512
#define Sq 4096
#define Dq 128
#define Vq 6
#define Kq 409

// Precomputed per-token-value tables
__device__ float g_score[Vq];
__device__ float g_attC1[Vq * 64];   // att_v @ C1  (classifier layer-1 fold)

#define CP_ASYNC16(dst_u32, src_ptr) \
    asm volatile("cp.async.cg.shared.global [%0], [%1], 16;\n" \
                 :: "r"(dst_u32), "l"(src_ptr))

// ---------------------------------------------------------------------------
// Kernel 1: precompute — 6 blocks (one per token value) x 256 threads.
// cp.async prefetch of W2/A2; C1 staged in registers; e via __ldg inside
// layer 1. Critical path ~1 DRAM round trip + smem compute.
// ---------------------------------------------------------------------------
__global__ __launch_bounds__(256) void precompute_kernel(
    const float* __restrict__ emb,
    const float* __restrict__ W1, const float* __restrict__ b1,
    const float* __restrict__ W2, const float* __restrict__ b2,
    const float* __restrict__ W3, const float* __restrict__ b3,
    const float* __restrict__ A1, const float* __restrict__ a1,
    const float* __restrict__ A2, const float* __restrict__ a2,
    const float* __restrict__ C1)
{
#if __CUDA_ARCH__ >= 900
    cudaTriggerProgrammaticLaunchCompletion();
#endif
    const int v = blockIdx.x;
    const int t = threadIdx.x;  // 256 threads

    __shared__ float sW2[64 * 32];    // 8 KB
    __shared__ float sA2[64 * Dq];    // 32 KB
    __shared__ float h1[64];
    __shared__ float g1[64];
    __shared__ float h2[32];
    __shared__ float att_s[Dq];

    // ---- phase 0: async weight prefetch (drains during layer 1) ----
    {
        unsigned w2base = (unsigned)__cvta_generic_to_shared(sW2);
        unsigned a2base = (unsigned)__cvta_generic_to_shared(sA2);
        #pragma unroll
        for (int i = 0; i < 2; i++) {
            const int c = t + i * 256;           // 512 chunks of 16B
            CP_ASYNC16(w2base + c * 16, (const float4*)W2 + c);
        }
        #pragma unroll
        for (int i = 0; i < 8; i++) {
            const int c = t + i * 256;           // 2048 chunks of 16B
            CP_ASYNC16(a2base + c * 16, (const float4*)A2 + c);
        }
        asm volatile("cp.async.commit_group;\n");
    }

    // ---- eager C1 register staging (consumed in the final attC1 stage) ----
    const int n4 = t >> 2, p4 = t & 3;
    float c1reg[32];
    #pragma unroll
    for (int i = 0; i < 32; i++)
        c1reg[i] = __ldg(&C1[(p4 * 32 + i) * 64 + n4]);

    // ---- layer 1: W1 and A1 paths; e via uniform __ldg ----
    {
        const int mat = t >> 7;          // 0 -> W1 path, 1 -> A1 path
        const int n   = (t & 127) >> 1;  // neuron 0..63
        const int p   = t & 1;           // half 0..1
        const float* M = mat ? A1 : W1;
        const float* ev = emb + v * Dq + p * 64;
        float s = 0.f;
        #pragma unroll
        for (int i = 0; i < 64; i++)
            s += __ldg(&ev[i]) * M[(p * 64 + i) * 64 + n];
        s += __shfl_xor_sync(0xffffffff, s, 1);
        if (p == 0) {
            if (mat == 0) h1[n] = fmaxf(s + b1[n], 0.f);
            else          g1[n] = fmaxf(s + a1[n], 0.f);
        }
    }
    asm volatile("cp.async.wait_group 0;\n" ::: "memory");
    __syncthreads();

    // ---- layer 2 (W2, smem): 32 neurons x 4 threads (threads 0..127) ----
    if (t < 128) {
        const int n = t >> 2, p = t & 3;
        float s = 0.f;
        const int base = p * 16;
        #pragma unroll
        for (int i = 0; i < 16; i++)
            s += h1[base + i] * sW2[(base + i) * 32 + n];
        s += __shfl_xor_sync(0xffffffff, s, 1);
        s += __shfl_xor_sync(0xffffffff, s, 2);
        if (p == 0) h2[n] = fmaxf(s + b2[n], 0.f);
    }
    // ---- A2 (smem): 128 outputs x 2 threads ----
    {
        const int j = t >> 1, p = t & 1;
        float s = 0.f;
        const int base = p * 32;
        #pragma unroll
        for (int i = 0; i < 32; i++)
            s += g1[base + i] * sA2[(base + i) * Dq + j];
        s += __shfl_xor_sync(0xffffffff, s, 1);
        if (p == 0) att_s[j] = s + a2[j];
    }
    __syncthreads();

    // ---- layer 3: warp 0 -> sigmoid score ----
    if (t < 32) {
        float z = h2[t] * W3[t];
        #pragma unroll
        for (int d = 16; d >= 1; d >>= 1) z += __shfl_xor_sync(0xffffffff, z, d);
        if (t == 0) g_score[v] = 1.f / (1.f + expf(-(z + b3[0])));
    }

    // ---- attC1[v][n] = att_v @ C1[:,n] (C1 from registers) ----
    {
        float s = 0.f;
        const int base = p4 * 32;
        #pragma unroll
        for (int i = 0; i < 32; i++)
            s += att_s[base + i] * c1reg[i];
        s += __shfl_xor_sync(0xffffffff, s, 1);
        s += __shfl_xor_sync(0xffffffff, s, 2);
        if (p4 == 0) g_attC1[v * 64 + n4] = s;
    }
}

// ---------------------------------------------------------------------------
// Kernel 2: one CTA per batch row. 256 threads, 16 contiguous tokens/thread.
// R13 structure; oidx scattered directly to global (no smem staging),
// single block barrier.
// ---------------------------------------------------------------------------
__global__ __launch_bounds__(256, 4) void main_kernel(
    const int* __restrict__ x,
    const float* __restrict__ c1,
    const float* __restrict__ C2, const float* __restrict__ c2,
    float* __restrict__ out)
{
    const int b = blockIdx.x;
    const int t = threadIdx.x;  // 256 threads
    const int w = t >> 5, l = t & 31;

    __shared__ unsigned long long wtot[8];  // per-warp packed totals

    // ---------- score-independent front half (overlaps precompute) ----------
    const int4* xb = (const int4*)(x + (size_t)b * Sq);

    int4 P[4];
    unsigned long long hist = 0ull;
    #pragma unroll
    for (int i = 0; i < 4; i++) {
        int4 p = xb[t * 4 + i];
        P[i] = p;
        hist += 1ull << (p.x * 10);
        hist += 1ull << (p.y * 10);
        hist += 1ull << (p.z * 10);
        hist += 1ull << (p.w * 10);
    }

    // warp-level packed inclusive scan (10-bit fields)
    unsigned long long run = hist;
    #pragma unroll
    for (int d = 1; d < 32; d <<= 1) {
        unsigned long long o = __shfl_up_sync(0xffffffff, run, d);
        if (l >= d) run += o;
    }
    const unsigned long long excl = run - hist;
    if (l == 31) wtot[w] = run;
    __syncthreads();  // barrier 1 (the only block barrier)

    // cross-warp: packed exclusive base (pcnt) + per-value block totals
    unsigned long long pcnt;
    int tot[Vq];
    {
        unsigned long long pre = 0ull, all = 0ull;
        #pragma unroll
        for (int ww = 0; ww < 8; ww++) {
            unsigned long long tw = wtot[ww];
            if (ww < w) pre += tw;
            all += tw;
        }
        pcnt = pre + excl;   // packed per-value rank counters for this thread
        #pragma unroll
        for (int v = 0; v < Vq; v++)
            tot[v] = (int)((all >> (v * 10)) & 0x3FF);
    }

    // ---------- wait for precompute results ----------
#if __CUDA_ARCH__ >= 900
    cudaGridDependencySynchronize();
#endif

    float sc[Vq];
    #pragma unroll
    for (int v = 0; v < Vq; v++) sc[v] = g_score[v];

    // lane-resident score for dynamic gather via shfl
    const int v_me = (l < Vq) ? l : (Vq - 1);
    const float scf = sc[v_me];

    // per-lane rank offset: offraw_l = sum of tot[u] for u preceding v_me
    // (u precedes v  <=>  s_u > s_v || (s_u == s_v && u < v))
    int offraw_lane = 0;
    #pragma unroll
    for (int u = 0; u < Vq; u++) {
        bool prec = (u != v_me) &&
                    ((sc[u] > sc[v_me]) || (sc[u] == sc[v_me] && u < v_me));
        offraw_lane += prec ? tot[u] : 0;
    }

    // ---------- fused fs-store + compaction (direct global scatter) ----------
    float* fs   = out + Bq + (size_t)Bq * Kq + (size_t)b * Sq;
    float* oidx = out + Bq + (size_t)b * Kq;
    #pragma unroll
    for (int i = 0; i < 4; i++) {
        const int* pv = (const int*)&P[i];
        float4 f;
        float* fp = (float*)&f;
        #pragma unroll
        for (int j = 0; j < 4; j++) {
            const int vv = pv[j];
            fp[j] = __shfl_sync(0xffffffff, scf, vv);
            const int ofr = __shfl_sync(0xffffffff, offraw_lane, vv);
            const int sh = vv * 10;
            const int rank = (int)((pcnt >> sh) & 0x3FF);
            pcnt += 1ull << sh;
            const int pos = ofr + rank;
            if (pos < Kq) oidx[pos] = (float)(t * 16 + i * 4 + j);
        }
        ((float4*)fs)[t * 4 + i] = f;
    }

    // ---------- folded classifier epilogue (warp 0 only; no barrier) ----------
    if (w == 0) {
        float takef[Vq];
        #pragma unroll
        for (int v = 0; v < Vq; v++) {
            const int ofr = __shfl_sync(0xffffffff, offraw_lane, v);
            takef[v] = (float)max(0, min(Kq - ofr, tot[v]));
        }
        const float invK = 1.f / (float)Kq;
        float zacc = 0.f;
        #pragma unroll
        for (int hh = 0; hh < 2; hh++) {
            const int n = l + hh * 32;
            float s = 0.f;
            #pragma unroll
            for (int v = 0; v < Vq; v++)
                s += takef[v] * g_attC1[v * 64 + n];
            const float h = fmaxf(fmaf(s, invK, c1[n]), 0.f);
            zacc += h * C2[n];
        }
        #pragma unroll
        for (int d = 16; d >= 1; d >>= 1)
            zacc += __shfl_xor_sync(0xffffffff, zacc, d);
        if (l == 0) out[b] = 1.f / (1.f + expf(-(zacc + c2[0])));
    }
}

extern "C" void kernel_launch(void* const* d_in, const int* in_sizes, int n_in,
                              void* d_out, int out_size) {
    const int*   x   = (const int*)d_in[0];
    const float* emb = (const float*)d_in[1];
    const float* W1  = (const float*)d_in[2];
    const float* b1  = (const float*)d_in[3];
    const float* W2  = (const float*)d_in[4];
    const float* b2  = (const float*)d_in[5];
    const float* W3  = (const float*)d_in[6];
    const float* b3  = (const float*)d_in[7];
    const float* A1  = (const float*)d_in[8];
    const float* a1  = (const float*)d_in[9];
    const float* A2  = (const float*)d_in[10];
    const float* a2  = (const float*)d_in[11];
    const float* C1  = (const float*)d_in[12];
    const float* c1  = (const float*)d_in[13];
    const float* C2  = (const float*)d_in[14];
    const float* c2  = (const float*)d_in[15];
    float* out = (float*)d_out;

    precompute_kernel<<<Vq, 256>>>(emb, W1, b1, W2, b2, W3, b3,
                                   A1, a1, A2, a2, C1);

    // PDL: main_kernel may begin before precompute finishes; it gates on
    // cudaGridDependencySynchronize() before consuming g_score/g_attC1.
    cudaLaunchConfig_t cfg = {};
    cfg.gridDim  = dim3(Bq, 1, 1);
    cfg.blockDim = dim3(256, 1, 1);
    cfg.dynamicSmemBytes = 0;
    cfg.stream = 0;
    cudaLaunchAttribute attr[1];
    attr[0].id = cudaLaunchAttributeProgrammaticStreamSerialization;
    attr[0].val.programmaticStreamSerializationAllowed = 1;
    cfg.attrs = attr;
    cfg.numAttrs = 1;
    cudaLaunchKernelEx(&cfg, main_kernel, x, c1, C2, c2, out);
}